// round 3
// baseline (speedup 1.0000x reference)
#include <cuda_runtime.h>
#include <cuda_bf16.h>
#include <math.h>

// Problem constants
#define BB 4
#define SS 2048
#define DD 1024
#define HH 16
#define DH 64

// ---------------------------------------------------------------------------
// Scratch (device globals — no runtime allocation allowed)
// ---------------------------------------------------------------------------
__device__ float g_qkv [(long)BB * SS * 3 * DD];   // [B,S,3D]
__device__ float g_hop [(long)BB * SS * SS];       // [B,S,S]
__device__ float g_attn[(long)BB * SS * DD];       // attention output (pre O-proj)
__device__ float g_att2[(long)BB * SS * DD];       // after O-proj
__device__ float g_x1  [(long)BB * SS * DD];       // after LN1
__device__ float g_ff1 [(long)BB * SS * 4 * DD];   // after FFN1+GELU
__device__ float g_ff2 [(long)BB * SS * DD];       // after FFN2

__device__ __forceinline__ float gelu_exact(float x) {
    return 0.5f * x * (1.0f + erff(x * 0.70710678118654752f));
}

__device__ __forceinline__ float to_tf32(float x) {
    asm("cvt.rna.tf32.f32 %0, %0;" : "+f"(x));
    return x;
}

__device__ __forceinline__ void mma_tf32(float* c, const float* a, const float* b) {
    asm volatile(
        "mma.sync.aligned.m16n8k8.row.col.f32.tf32.tf32.f32 "
        "{%0,%1,%2,%3}, {%4,%5,%6,%7}, {%8,%9}, {%0,%1,%2,%3};"
        : "+f"(c[0]), "+f"(c[1]), "+f"(c[2]), "+f"(c[3])
        : "r"(__float_as_uint(a[0])), "r"(__float_as_uint(a[1])),
          "r"(__float_as_uint(a[2])), "r"(__float_as_uint(a[3])),
          "r"(__float_as_uint(b[0])), "r"(__float_as_uint(b[1])));
}

// ---------------------------------------------------------------------------
// TF32 tensor-core GEMM: C[M,N] = scale * (A[M,K] @ B[N,K]^T) + bias[N],
// optional exact GELU. 128x128x32 tiles, 256 threads (8 warps, 2x4 layout,
// each warp a 64x32 output tile via m16n8k8 tf32 mma).
// Requires M%128==0, N%128==0, K%32==0 (true at all call sites).
// causal!=0 => skip tiles with n0 > m0+127 (hopping matrix).
// ---------------------------------------------------------------------------
#define SPAD 36
template<bool GELU>
__global__ __launch_bounds__(256, 2)
void sgemm_bt(const float* __restrict__ A, const float* __restrict__ B,
              const float* __restrict__ bias, float* __restrict__ C,
              int M, int N, int K,
              long sA, long sB, long sC, float scale, int causal)
{
    __shared__ float As[128][SPAD];   // [m][k] tf32 values
    __shared__ float Bs[128][SPAD];   // [n][k] tf32 values

    const int tid  = threadIdx.x;
    const int warp = tid >> 5;
    const int lane = tid & 31;
    const int g    = lane >> 2;   // quad group 0..7
    const int t    = lane & 3;    // thread-in-quad
    const int m0   = blockIdx.y * 128;
    const int n0   = blockIdx.x * 128;

    if (causal && n0 > m0 + 127) return;

    const int z = blockIdx.z;
    A += (long)z * sA;
    B += (long)z * sB;
    C += (long)z * sC;

    const int wm = (warp & 1) * 64;   // warp m offset
    const int wn = (warp >> 1) * 32;  // warp n offset

    float acc[4][4][4];               // [mi][ni][c0..c3]
    #pragma unroll
    for (int mi = 0; mi < 4; mi++)
        #pragma unroll
        for (int ni = 0; ni < 4; ni++)
            #pragma unroll
            for (int c = 0; c < 4; c++)
                acc[mi][ni][c] = 0.0f;

    // Per-thread staging coordinates for the cooperative tile loads:
    // 1024 float4s per 128x32 tile, 4 per thread.
    const int lr = tid >> 3;          // row 0..31 base (advances by 32 per l)
    const int lc = (tid & 7) * 4;     // col 0,4,...,28

    for (int k0 = 0; k0 < K; k0 += 32) {
        #pragma unroll
        for (int l = 0; l < 4; l++) {
            int r = lr + l * 32;
            float4 va = *(const float4*)&A[(long)(m0 + r) * K + k0 + lc];
            As[r][lc+0] = to_tf32(va.x);
            As[r][lc+1] = to_tf32(va.y);
            As[r][lc+2] = to_tf32(va.z);
            As[r][lc+3] = to_tf32(va.w);
            float4 vb = *(const float4*)&B[(long)(n0 + r) * K + k0 + lc];
            Bs[r][lc+0] = to_tf32(vb.x);
            Bs[r][lc+1] = to_tf32(vb.y);
            Bs[r][lc+2] = to_tf32(vb.z);
            Bs[r][lc+3] = to_tf32(vb.w);
        }
        __syncthreads();

        #pragma unroll
        for (int ks = 0; ks < 4; ks++) {
            const int kb = ks * 8;
            float a[4][4], b[4][2];
            #pragma unroll
            for (int mi = 0; mi < 4; mi++) {
                const int row = wm + mi * 16;
                a[mi][0] = As[row + g    ][kb + t    ];
                a[mi][1] = As[row + g + 8][kb + t    ];
                a[mi][2] = As[row + g    ][kb + t + 4];
                a[mi][3] = As[row + g + 8][kb + t + 4];
            }
            #pragma unroll
            for (int ni = 0; ni < 4; ni++) {
                const int col = wn + ni * 8;
                b[ni][0] = Bs[col + g][kb + t    ];
                b[ni][1] = Bs[col + g][kb + t + 4];
            }
            #pragma unroll
            for (int mi = 0; mi < 4; mi++)
                #pragma unroll
                for (int ni = 0; ni < 4; ni++)
                    mma_tf32(acc[mi][ni], a[mi], b[ni]);
        }
        __syncthreads();
    }

    // Epilogue: c0,c1 at (g, 2t),(g, 2t+1); c2,c3 at (g+8, same cols)
    #pragma unroll
    for (int mi = 0; mi < 4; mi++) {
        const int row0 = m0 + wm + mi * 16 + g;
        #pragma unroll
        for (int ni = 0; ni < 4; ni++) {
            const int col = n0 + wn + ni * 8 + 2 * t;
            float bx = 0.0f, by = 0.0f;
            if (bias) { bx = bias[col]; by = bias[col + 1]; }
            float o0 = acc[mi][ni][0] * scale + bx;
            float o1 = acc[mi][ni][1] * scale + by;
            float o2 = acc[mi][ni][2] * scale + bx;
            float o3 = acc[mi][ni][3] * scale + by;
            if (GELU) {
                o0 = gelu_exact(o0); o1 = gelu_exact(o1);
                o2 = gelu_exact(o2); o3 = gelu_exact(o3);
            }
            *(float2*)&C[(long)row0 * N + col]       = make_float2(o0, o1);
            *(float2*)&C[(long)(row0 + 8) * N + col] = make_float2(o2, o3);
        }
    }
}

// ---------------------------------------------------------------------------
// Flash-style causal attention with hopping bias.
// Grid: (S/64, H, B). Block: 256 threads (16x16). 64-row q tile, dh=64.
// Dynamic smem: QT/KT/Vs/PT each [64][68] floats = 69632 bytes.
// ---------------------------------------------------------------------------
#define APAD 68
__global__ __launch_bounds__(256)
void attn_kernel(const float* __restrict__ qkv, const float* __restrict__ hop,
                 float* __restrict__ out)
{
    extern __shared__ float sm[];
    float* QT = sm;                 // QT[d][q]
    float* KT = sm + 64 * APAD;     // KT[d][k]
    float* Vs = sm + 2 * 64 * APAD; // Vs[k][d]
    float* PT = sm + 3 * 64 * APAD; // PT[k][q]

    const int tid = threadIdx.x;
    const int tx  = tid & 15;
    const int ty  = tid >> 4;
    const int qt  = blockIdx.x;
    const int h   = blockIdx.y;
    const int b   = blockIdx.z;
    const int q0  = qt * 64;

    const long rowbase = (long)b * SS * (3 * DD);

    // Load Q tile (transposed into QT)
    #pragma unroll
    for (int l = 0; l < 4; l++) {
        int f  = tid + l * 256;     // 0..1023
        int r  = f >> 4;            // q row 0..63
        int dc = f & 15;            // float4 column
        float4 v = *(const float4*)&qkv[rowbase + (long)(q0 + r) * (3 * DD) + h * DH + dc * 4];
        QT[(dc*4+0) * APAD + r] = v.x;
        QT[(dc*4+1) * APAD + r] = v.y;
        QT[(dc*4+2) * APAD + r] = v.z;
        QT[(dc*4+3) * APAD + r] = v.w;
    }

    float m[4], lsum[4], acc[4][4];
    #pragma unroll
    for (int i = 0; i < 4; i++) {
        m[i] = -1e30f;
        lsum[i] = 0.0f;
        #pragma unroll
        for (int j = 0; j < 4; j++) acc[i][j] = 0.0f;
    }

    const float isq = 0.125f;  // 1/sqrt(dh)
    const long hb = (long)b * SS * SS;

    for (int kt = 0; kt <= qt; kt++) {
        const int k0 = kt * 64;

        // Load K (transposed) and V tiles
        #pragma unroll
        for (int l = 0; l < 4; l++) {
            int f  = tid + l * 256;
            int r  = f >> 4;
            int dc = f & 15;
            long base = rowbase + (long)(k0 + r) * (3 * DD) + h * DH + dc * 4;
            float4 kv = *(const float4*)&qkv[base + DD];
            KT[(dc*4+0) * APAD + r] = kv.x;
            KT[(dc*4+1) * APAD + r] = kv.y;
            KT[(dc*4+2) * APAD + r] = kv.z;
            KT[(dc*4+3) * APAD + r] = kv.w;
            float4 vv = *(const float4*)&qkv[base + 2 * DD];
            *(float4*)&Vs[r * APAD + dc * 4] = vv;
        }
        __syncthreads();

        // S = Q @ K^T  (4x4 per thread)
        float s[4][4];
        #pragma unroll
        for (int i = 0; i < 4; i++)
            #pragma unroll
            for (int j = 0; j < 4; j++) s[i][j] = 0.0f;

        #pragma unroll 16
        for (int d = 0; d < 64; d++) {
            float4 a  = *(const float4*)&QT[d * APAD + ty * 4];
            float4 bv = *(const float4*)&KT[d * APAD + tx * 4];
            const float* ap = &a.x;
            const float* bp = &bv.x;
            #pragma unroll
            for (int i = 0; i < 4; i++)
                #pragma unroll
                for (int j = 0; j < 4; j++)
                    s[i][j] += ap[i] * bp[j];
        }

        // bias + mask + online softmax (per q row; 16 tx threads share a row)
        #pragma unroll
        for (int i = 0; i < 4; i++) {
            const int rg = q0 + ty * 4 + i;
            float4 hv = *(const float4*)&hop[hb + (long)rg * SS + k0 + tx * 4];
            const float* hp = &hv.x;
            float sv[4];
            #pragma unroll
            for (int j = 0; j < 4; j++) {
                sv[j] = s[i][j] * isq + hp[j];
                if (k0 + tx * 4 + j > rg) sv[j] = -1e30f;
            }
            float rm = fmaxf(fmaxf(sv[0], sv[1]), fmaxf(sv[2], sv[3]));
            #pragma unroll
            for (int o = 8; o > 0; o >>= 1)
                rm = fmaxf(rm, __shfl_xor_sync(0xffffffffu, rm, o));

            float nm  = fmaxf(m[i], rm);
            float scl = __expf(m[i] - nm);
            float p[4], rs = 0.0f;
            #pragma unroll
            for (int j = 0; j < 4; j++) {
                p[j] = __expf(sv[j] - nm);
                rs += p[j];
            }
            #pragma unroll
            for (int o = 8; o > 0; o >>= 1)
                rs += __shfl_xor_sync(0xffffffffu, rs, o);

            lsum[i] = lsum[i] * scl + rs;
            m[i]    = nm;
            #pragma unroll
            for (int j = 0; j < 4; j++) acc[i][j] *= scl;
            #pragma unroll
            for (int j = 0; j < 4; j++)
                PT[(tx * 4 + j) * APAD + ty * 4 + i] = p[j];
        }
        __syncthreads();

        // O += P @ V
        #pragma unroll 16
        for (int k = 0; k < 64; k++) {
            float4 a  = *(const float4*)&PT[k * APAD + ty * 4];
            float4 bv = *(const float4*)&Vs[k * APAD + tx * 4];
            const float* ap = &a.x;
            const float* bp = &bv.x;
            #pragma unroll
            for (int i = 0; i < 4; i++)
                #pragma unroll
                for (int j = 0; j < 4; j++)
                    acc[i][j] += ap[i] * bp[j];
        }
        __syncthreads();
    }

    // Write out: [B,S,H*dh]
    #pragma unroll
    for (int i = 0; i < 4; i++) {
        const int rg = q0 + ty * 4 + i;
        const float inv = 1.0f / lsum[i];
        float4 o;
        o.x = acc[i][0] * inv;
        o.y = acc[i][1] * inv;
        o.z = acc[i][2] * inv;
        o.w = acc[i][3] * inv;
        *(float4*)&out[((long)b * SS + rg) * DD + h * DH + tx * 4] = o;
    }
}

// ---------------------------------------------------------------------------
// Fused residual + LayerNorm. One block per row of 1024.
// out = LN(resid + y) * g + beta
// ---------------------------------------------------------------------------
__global__ __launch_bounds__(256)
void ln_kernel(const float* __restrict__ resid, const float* __restrict__ y,
               const float* __restrict__ g, const float* __restrict__ beta,
               float* __restrict__ out)
{
    __shared__ float red[16];
    __shared__ float stats[2];

    const long row = blockIdx.x;
    const int tid  = threadIdx.x;
    const long base = row * DD + tid * 4;

    float4 r  = *(const float4*)&resid[base];
    float4 yv = *(const float4*)&y[base];
    float v0 = r.x + yv.x, v1 = r.y + yv.y, v2 = r.z + yv.z, v3 = r.w + yv.w;

    float s  = v0 + v1 + v2 + v3;
    float ss = v0*v0 + v1*v1 + v2*v2 + v3*v3;
    #pragma unroll
    for (int o = 16; o > 0; o >>= 1) {
        s  += __shfl_xor_sync(0xffffffffu, s, o);
        ss += __shfl_xor_sync(0xffffffffu, ss, o);
    }
    const int warp = tid >> 5;
    if ((tid & 31) == 0) {
        red[warp * 2]     = s;
        red[warp * 2 + 1] = ss;
    }
    __syncthreads();
    if (tid == 0) {
        float ts = 0.f, tss = 0.f;
        #pragma unroll
        for (int w = 0; w < 8; w++) { ts += red[w*2]; tss += red[w*2+1]; }
        float mean = ts * (1.0f / DD);
        float var  = tss * (1.0f / DD) - mean * mean;
        stats[0] = mean;
        stats[1] = rsqrtf(var + 1e-5f);
    }
    __syncthreads();
    const float mean = stats[0];
    const float istd = stats[1];

    float4 gv = *(const float4*)&g[tid * 4];
    float4 bv = *(const float4*)&beta[tid * 4];
    float4 o;
    o.x = (v0 - mean) * istd * gv.x + bv.x;
    o.y = (v1 - mean) * istd * gv.y + bv.y;
    o.z = (v2 - mean) * istd * gv.z + bv.z;
    o.w = (v3 - mean) * istd * gv.w + bv.w;
    *(float4*)&out[base] = o;
}

// ---------------------------------------------------------------------------
// Launcher
// ---------------------------------------------------------------------------
extern "C" void kernel_launch(void* const* d_in, const int* in_sizes, int n_in,
                              void* d_out, int out_size)
{
    const float* x      = (const float*)d_in[0];
    const float* imag   = (const float*)d_in[1];
    const float* w_qkv  = (const float*)d_in[2];
    const float* b_qkv  = (const float*)d_in[3];
    const float* w_o    = (const float*)d_in[4];
    const float* b_o    = (const float*)d_in[5];
    const float* ln1_g  = (const float*)d_in[6];
    const float* ln1_b  = (const float*)d_in[7];
    const float* w1     = (const float*)d_in[8];
    const float* b1     = (const float*)d_in[9];
    const float* w2     = (const float*)d_in[10];
    const float* b2     = (const float*)d_in[11];
    const float* ln2_g  = (const float*)d_in[12];
    const float* ln2_b  = (const float*)d_in[13];
    float* out = (float*)d_out;

    float *qkvp, *hopp, *attnp, *att2p, *x1p, *f1p, *f2p;
    cudaGetSymbolAddress((void**)&qkvp,  g_qkv);
    cudaGetSymbolAddress((void**)&hopp,  g_hop);
    cudaGetSymbolAddress((void**)&attnp, g_attn);
    cudaGetSymbolAddress((void**)&att2p, g_att2);
    cudaGetSymbolAddress((void**)&x1p,   g_x1);
    cudaGetSymbolAddress((void**)&f1p,   g_ff1);
    cudaGetSymbolAddress((void**)&f2p,   g_ff2);

    cudaFuncSetAttribute(attn_kernel,
                         cudaFuncAttributeMaxDynamicSharedMemorySize,
                         4 * 64 * APAD * sizeof(float));

    const int MR = BB * SS;  // 8192 rows

    // 1) hopping[b] = imag[b] @ imag[b]^T / sqrt(D)  (lower-triangular tiles only)
    sgemm_bt<false><<<dim3(SS/128, SS/128, BB), 256>>>(
        imag, imag, nullptr, hopp, SS, SS, DD,
        (long)SS * DD, (long)SS * DD, (long)SS * SS, 0.03125f, 1);

    // 2) QKV projection
    sgemm_bt<false><<<dim3(3*DD/128, MR/128, 1), 256>>>(
        x, w_qkv, b_qkv, qkvp, MR, 3*DD, DD, 0, 0, 0, 1.0f, 0);

    // 3) Causal attention with hopping bias
    attn_kernel<<<dim3(SS/64, HH, BB), 256, 4 * 64 * APAD * sizeof(float)>>>(
        qkvp, hopp, attnp);

    // 4) Output projection
    sgemm_bt<false><<<dim3(DD/128, MR/128, 1), 256>>>(
        attnp, w_o, b_o, att2p, MR, DD, DD, 0, 0, 0, 1.0f, 0);

    // 5) LN1(x + attn_out)
    ln_kernel<<<MR, 256>>>(x, att2p, ln1_g, ln1_b, x1p);

    // 6) FFN1 + exact GELU
    sgemm_bt<true><<<dim3(4*DD/128, MR/128, 1), 256>>>(
        x1p, w1, b1, f1p, MR, 4*DD, DD, 0, 0, 0, 1.0f, 0);

    // 7) FFN2
    sgemm_bt<false><<<dim3(DD/128, MR/128, 1), 256>>>(
        f1p, w2, b2, f2p, MR, DD, 4*DD, 0, 0, 0, 1.0f, 0);

    // 8) LN2(x1 + ffn_out) -> output
    ln_kernel<<<MR, 256>>>(x1p, f2p, ln2_g, ln2_b, out);
}

// round 5
// speedup vs baseline: 1.6193x; 1.6193x over previous
#include <cuda_runtime.h>
#include <cuda_bf16.h>
#include <cstdint>
#include <math.h>

// Problem constants
#define BB 4
#define SS 2048
#define DD 1024
#define HH 16
#define DH 64

// ---------------------------------------------------------------------------
// Scratch (device globals — no runtime allocation allowed)
// ---------------------------------------------------------------------------
__device__ float g_qkv [(long)BB * SS * 3 * DD];   // [B,S,3D]
__device__ float g_hop [(long)BB * SS * SS];       // [B,S,S]
__device__ float g_attn[(long)BB * SS * DD];       // attention output (pre O-proj)
__device__ float g_att2[(long)BB * SS * DD];       // after O-proj
__device__ float g_x1  [(long)BB * SS * DD];       // after LN1
__device__ float g_ff1 [(long)BB * SS * 4 * DD];   // after FFN1+GELU
__device__ float g_ff2 [(long)BB * SS * DD];       // after FFN2

__device__ __forceinline__ float gelu_exact(float x) {
    return 0.5f * x * (1.0f + erff(x * 0.70710678118654752f));
}

__device__ __forceinline__ void mma_tf32(float* c, const float* a, const float* b) {
    asm volatile(
        "mma.sync.aligned.m16n8k8.row.col.f32.tf32.tf32.f32 "
        "{%0,%1,%2,%3}, {%4,%5,%6,%7}, {%8,%9}, {%0,%1,%2,%3};"
        : "+f"(c[0]), "+f"(c[1]), "+f"(c[2]), "+f"(c[3])
        : "r"(__float_as_uint(a[0])), "r"(__float_as_uint(a[1])),
          "r"(__float_as_uint(a[2])), "r"(__float_as_uint(a[3])),
          "r"(__float_as_uint(b[0])), "r"(__float_as_uint(b[1])));
}

__device__ __forceinline__ void cp_async16(void* smem, const void* gmem) {
    unsigned int s = (unsigned int)__cvta_generic_to_shared(smem);
    asm volatile("cp.async.cg.shared.global [%0], [%1], 16;" :: "r"(s), "l"(gmem));
}
__device__ __forceinline__ void cp_commit() {
    asm volatile("cp.async.commit_group;");
}
template<int N> __device__ __forceinline__ void cp_wait() {
    asm volatile("cp.async.wait_group %0;" :: "n"(N));
}

// ---------------------------------------------------------------------------
// TF32 tensor-core GEMM with 3-stage cp.async pipeline.
// C[M,N] = scale * (A[M,K] @ B[N,K]^T) + bias[N], optional exact GELU.
// 128x128x32 tiles, 256 threads (8 warps, 2x4 layout, 64x32 warp tile).
// tf32 inputs by hardware truncation of fp32 bits (no explicit cvt).
// Requires M%128==0, N%128==0, K%32==0. causal!=0 => skip upper tiles.
// ---------------------------------------------------------------------------
#define SPAD 36
#define GSTAGE 3
#define GEMM_SMEM (GSTAGE * 2 * 128 * SPAD * (int)sizeof(float))

template<bool GELU>
__global__ __launch_bounds__(256, 2)
void sgemm_bt(const float* __restrict__ A, const float* __restrict__ B,
              const float* __restrict__ bias, float* __restrict__ C,
              int M, int N, int K,
              long sA, long sB, long sC, float scale, int causal)
{
    extern __shared__ float smem[];
    float* AsBase = smem;                       // [GSTAGE][128][SPAD]
    float* BsBase = smem + GSTAGE * 128 * SPAD;

    const int tid  = threadIdx.x;
    const int warp = tid >> 5;
    const int lane = tid & 31;
    const int g    = lane >> 2;   // quad group 0..7
    const int t    = lane & 3;    // thread-in-quad
    const int m0   = blockIdx.y * 128;
    const int n0   = blockIdx.x * 128;

    if (causal && n0 > m0 + 127) return;

    const int z = blockIdx.z;
    A += (long)z * sA;
    B += (long)z * sB;
    C += (long)z * sC;

    const int wm = (warp & 1) * 64;   // warp m offset
    const int wn = (warp >> 1) * 32;  // warp n offset

    float acc[4][4][4];
    #pragma unroll
    for (int mi = 0; mi < 4; mi++)
        #pragma unroll
        for (int ni = 0; ni < 4; ni++)
            #pragma unroll
            for (int c = 0; c < 4; c++)
                acc[mi][ni][c] = 0.0f;

    const int lr = tid >> 3;          // row base 0..31
    const int lc = (tid & 7) * 4;     // col 0,4,...,28
    const int niter = K >> 5;

    // stage(s, k0): issue cp.async copies of the 128x32 A and B tiles
    #define STAGE(s, k0)                                                      \
        {                                                                     \
            float* Ad = AsBase + (s) * 128 * SPAD;                            \
            float* Bd = BsBase + (s) * 128 * SPAD;                            \
            _Pragma("unroll")                                                 \
            for (int l = 0; l < 4; l++) {                                     \
                int r = lr + l * 32;                                          \
                cp_async16(&Ad[r * SPAD + lc], &A[(long)(m0 + r) * K + (k0) + lc]); \
                cp_async16(&Bd[r * SPAD + lc], &B[(long)(n0 + r) * K + (k0) + lc]); \
            }                                                                 \
        }

    STAGE(0, 0); cp_commit();
    STAGE(1, 32); cp_commit();

    int cur = 0;
    for (int i = 0; i < niter; i++) {
        cp_wait<1>();
        __syncthreads();

        const float* Ac = AsBase + cur * 128 * SPAD;
        const float* Bc = BsBase + cur * 128 * SPAD;

        #pragma unroll
        for (int ks = 0; ks < 4; ks++) {
            const int kb = ks * 8;
            float a[4][4], b[4][2];
            #pragma unroll
            for (int mi = 0; mi < 4; mi++) {
                const int row = wm + mi * 16;
                a[mi][0] = Ac[(row + g    ) * SPAD + kb + t    ];
                a[mi][1] = Ac[(row + g + 8) * SPAD + kb + t    ];
                a[mi][2] = Ac[(row + g    ) * SPAD + kb + t + 4];
                a[mi][3] = Ac[(row + g + 8) * SPAD + kb + t + 4];
            }
            #pragma unroll
            for (int ni = 0; ni < 4; ni++) {
                const int col = wn + ni * 8;
                b[ni][0] = Bc[(col + g) * SPAD + kb + t    ];
                b[ni][1] = Bc[(col + g) * SPAD + kb + t + 4];
            }
            #pragma unroll
            for (int mi = 0; mi < 4; mi++)
                #pragma unroll
                for (int ni = 0; ni < 4; ni++)
                    mma_tf32(acc[mi][ni], a[mi], b[ni]);
        }

        if (i + 2 < niter) {
            int s = (cur + 2) % GSTAGE;
            STAGE(s, (i + 2) * 32);
        }
        cp_commit();   // commit (possibly empty) keeps group accounting uniform
        cur = (cur + 1) % GSTAGE;
    }
    #undef STAGE

    // Epilogue: c0,c1 at (g, 2t),(g, 2t+1); c2,c3 at (g+8, same cols)
    #pragma unroll
    for (int mi = 0; mi < 4; mi++) {
        const int row0 = m0 + wm + mi * 16 + g;
        #pragma unroll
        for (int ni = 0; ni < 4; ni++) {
            const int col = n0 + wn + ni * 8 + 2 * t;
            float bx = 0.0f, by = 0.0f;
            if (bias) { bx = bias[col]; by = bias[col + 1]; }
            float o0 = acc[mi][ni][0] * scale + bx;
            float o1 = acc[mi][ni][1] * scale + by;
            float o2 = acc[mi][ni][2] * scale + bx;
            float o3 = acc[mi][ni][3] * scale + by;
            if (GELU) {
                o0 = gelu_exact(o0); o1 = gelu_exact(o1);
                o2 = gelu_exact(o2); o3 = gelu_exact(o3);
            }
            *(float2*)&C[(long)row0 * N + col]       = make_float2(o0, o1);
            *(float2*)&C[(long)(row0 + 8) * N + col] = make_float2(o2, o3);
        }
    }
}

// ---------------------------------------------------------------------------
// Tensor-core flash attention with hopping bias.
// Grid: (S/64, H, B). Block: 128 threads (4 warps).
// Each warp owns 16 q-rows x full 64-col k-tile -> warp-local online softmax.
// Q fragments live in registers for the whole loop. S=QK^T and O+=PV via
// m16n8k8 tf32 mma. P rearranged C-frag -> A-frag via quad shuffles.
// ---------------------------------------------------------------------------
__global__ __launch_bounds__(128, 3)
void attn_kernel(const float* __restrict__ qkv, const float* __restrict__ hop,
                 float* __restrict__ out)
{
    __shared__ float Ks[64][68];   // [key][d]  (also used to stage Q)
    __shared__ float Vt[64][68];   // [d][key]

    const int tid  = threadIdx.x;
    const int lane = tid & 31;
    const int warp = tid >> 5;
    const int g    = lane >> 2;
    const int t    = lane & 3;
    const int qt = blockIdx.x, h = blockIdx.y, b = blockIdx.z;
    const int q0 = qt * 64;
    const long rowbase = (long)b * SS * (3 * DD);
    const long hb      = (long)b * SS * SS;
    const int rg0 = q0 + warp * 16 + g;   // first owned row
    const int rg1 = rg0 + 8;              // second owned row

    // ---- Stage Q through Ks, pull A-fragments into registers ----
    #pragma unroll
    for (int l = 0; l < 8; l++) {
        int idx = tid + l * 128, r = idx >> 4, c = (idx & 15) * 4;
        *(float4*)&Ks[r][c] =
            *(const float4*)&qkv[rowbase + (long)(q0 + r) * (3 * DD) + h * DH + c];
    }
    __syncthreads();
    float qa[8][4];
    #pragma unroll
    for (int ks = 0; ks < 8; ks++) {
        qa[ks][0] = Ks[warp * 16 + g    ][ks * 8 + t    ];
        qa[ks][1] = Ks[warp * 16 + g + 8][ks * 8 + t    ];
        qa[ks][2] = Ks[warp * 16 + g    ][ks * 8 + t + 4];
        qa[ks][3] = Ks[warp * 16 + g + 8][ks * 8 + t + 4];
    }
    __syncthreads();

    float mr0 = -1e30f, mr1 = -1e30f, ls0 = 0.0f, ls1 = 0.0f;
    float oacc[8][4];
    #pragma unroll
    for (int ni = 0; ni < 8; ni++)
        #pragma unroll
        for (int c = 0; c < 4; c++) oacc[ni][c] = 0.0f;

    const int srcA = (lane & ~3) | (t >> 1);
    const int srcB = srcA + 2;

    for (int kt = 0; kt <= qt; kt++) {
        const int k0 = kt * 64;

        // Stage K (row-major) and V (transposed)
        #pragma unroll
        for (int l = 0; l < 8; l++) {
            int idx = tid + l * 128, r = idx >> 4, c = (idx & 15) * 4;
            long base = rowbase + (long)(k0 + r) * (3 * DD) + h * DH + c;
            *(float4*)&Ks[r][c] = *(const float4*)&qkv[base + DD];
            float4 v = *(const float4*)&qkv[base + 2 * DD];
            Vt[c + 0][r] = v.x; Vt[c + 1][r] = v.y;
            Vt[c + 2][r] = v.z; Vt[c + 3][r] = v.w;
        }
        __syncthreads();

        // Prefetch hopping bias for this tile (overlaps with S mma)
        float2 hp0[8], hp1[8];
        #pragma unroll
        for (int ni = 0; ni < 8; ni++) {
            hp0[ni] = *(const float2*)&hop[hb + (long)rg0 * SS + k0 + ni * 8 + 2 * t];
            hp1[ni] = *(const float2*)&hop[hb + (long)rg1 * SS + k0 + ni * 8 + 2 * t];
        }

        // S = Q @ K^T
        float sacc[8][4];
        #pragma unroll
        for (int ni = 0; ni < 8; ni++)
            #pragma unroll
            for (int c = 0; c < 4; c++) sacc[ni][c] = 0.0f;
        #pragma unroll
        for (int ks = 0; ks < 8; ks++) {
            #pragma unroll
            for (int ni = 0; ni < 8; ni++) {
                float bb[2] = { Ks[ni * 8 + g][ks * 8 + t],
                                Ks[ni * 8 + g][ks * 8 + t + 4] };
                mma_tf32(sacc[ni], qa[ks], bb);
            }
        }

        // scale + bias (+ causal mask on diagonal tile)
        #pragma unroll
        for (int ni = 0; ni < 8; ni++) {
            sacc[ni][0] = sacc[ni][0] * 0.125f + hp0[ni].x;
            sacc[ni][1] = sacc[ni][1] * 0.125f + hp0[ni].y;
            sacc[ni][2] = sacc[ni][2] * 0.125f + hp1[ni].x;
            sacc[ni][3] = sacc[ni][3] * 0.125f + hp1[ni].y;
        }
        if (kt == qt) {
            const int lr0 = warp * 16 + g, lr1 = lr0 + 8;
            #pragma unroll
            for (int ni = 0; ni < 8; ni++) {
                int c0 = ni * 8 + 2 * t, c1 = c0 + 1;
                if (c0 > lr0) sacc[ni][0] = -1e30f;
                if (c1 > lr0) sacc[ni][1] = -1e30f;
                if (c0 > lr1) sacc[ni][2] = -1e30f;
                if (c1 > lr1) sacc[ni][3] = -1e30f;
            }
        }

        // Online softmax (warp-local: rows owned by quads, reduce over t)
        float rm0 = -1e30f, rm1 = -1e30f;
        #pragma unroll
        for (int ni = 0; ni < 8; ni++) {
            rm0 = fmaxf(rm0, fmaxf(sacc[ni][0], sacc[ni][1]));
            rm1 = fmaxf(rm1, fmaxf(sacc[ni][2], sacc[ni][3]));
        }
        rm0 = fmaxf(rm0, __shfl_xor_sync(0xffffffffu, rm0, 1));
        rm0 = fmaxf(rm0, __shfl_xor_sync(0xffffffffu, rm0, 2));
        rm1 = fmaxf(rm1, __shfl_xor_sync(0xffffffffu, rm1, 1));
        rm1 = fmaxf(rm1, __shfl_xor_sync(0xffffffffu, rm1, 2));

        const float nm0 = fmaxf(mr0, rm0), nm1 = fmaxf(mr1, rm1);
        const float sc0 = __expf(mr0 - nm0), sc1 = __expf(mr1 - nm1);
        float rs0 = 0.0f, rs1 = 0.0f;
        #pragma unroll
        for (int ni = 0; ni < 8; ni++) {
            sacc[ni][0] = __expf(sacc[ni][0] - nm0);
            sacc[ni][1] = __expf(sacc[ni][1] - nm0);
            sacc[ni][2] = __expf(sacc[ni][2] - nm1);
            sacc[ni][3] = __expf(sacc[ni][3] - nm1);
            rs0 += sacc[ni][0] + sacc[ni][1];
            rs1 += sacc[ni][2] + sacc[ni][3];
        }
        rs0 += __shfl_xor_sync(0xffffffffu, rs0, 1);
        rs0 += __shfl_xor_sync(0xffffffffu, rs0, 2);
        rs1 += __shfl_xor_sync(0xffffffffu, rs1, 1);
        rs1 += __shfl_xor_sync(0xffffffffu, rs1, 2);

        ls0 = ls0 * sc0 + rs0;  mr0 = nm0;
        ls1 = ls1 * sc1 + rs1;  mr1 = nm1;
        #pragma unroll
        for (int ni = 0; ni < 8; ni++) {
            oacc[ni][0] *= sc0; oacc[ni][1] *= sc0;
            oacc[ni][2] *= sc1; oacc[ni][3] *= sc1;
        }

        // O += P @ V : rearrange P C-frags -> A-frags via quad shuffles
        #pragma unroll
        for (int ks2 = 0; ks2 < 8; ks2++) {
            float s0 = __shfl_sync(0xffffffffu, sacc[ks2][0], srcA);
            float s1 = __shfl_sync(0xffffffffu, sacc[ks2][1], srcA);
            float s2 = __shfl_sync(0xffffffffu, sacc[ks2][2], srcA);
            float s3 = __shfl_sync(0xffffffffu, sacc[ks2][3], srcA);
            float u0 = __shfl_sync(0xffffffffu, sacc[ks2][0], srcB);
            float u1 = __shfl_sync(0xffffffffu, sacc[ks2][1], srcB);
            float u2 = __shfl_sync(0xffffffffu, sacc[ks2][2], srcB);
            float u3 = __shfl_sync(0xffffffffu, sacc[ks2][3], srcB);
            float pa[4];
            pa[0] = (t & 1) ? s1 : s0;   // P[g   ][8ks2+t  ]
            pa[1] = (t & 1) ? s3 : s2;   // P[g+8 ][8ks2+t  ]
            pa[2] = (t & 1) ? u1 : u0;   // P[g   ][8ks2+t+4]
            pa[3] = (t & 1) ? u3 : u2;   // P[g+8 ][8ks2+t+4]
            #pragma unroll
            for (int ni = 0; ni < 8; ni++) {
                float bb[2] = { Vt[ni * 8 + g][ks2 * 8 + t],
                                Vt[ni * 8 + g][ks2 * 8 + t + 4] };
                mma_tf32(oacc[ni], pa, bb);
            }
        }
        __syncthreads();
    }

    // Epilogue
    const float inv0 = 1.0f / ls0, inv1 = 1.0f / ls1;
    #pragma unroll
    for (int ni = 0; ni < 8; ni++) {
        const int col = h * DH + ni * 8 + 2 * t;
        *(float2*)&out[((long)b * SS + rg0) * DD + col] =
            make_float2(oacc[ni][0] * inv0, oacc[ni][1] * inv0);
        *(float2*)&out[((long)b * SS + rg1) * DD + col] =
            make_float2(oacc[ni][2] * inv1, oacc[ni][3] * inv1);
    }
}

// ---------------------------------------------------------------------------
// Fused residual + LayerNorm. One block per row of 1024.
// ---------------------------------------------------------------------------
__global__ __launch_bounds__(256)
void ln_kernel(const float* __restrict__ resid, const float* __restrict__ y,
               const float* __restrict__ g, const float* __restrict__ beta,
               float* __restrict__ out)
{
    __shared__ float red[16];
    __shared__ float stats[2];

    const long row = blockIdx.x;
    const int tid  = threadIdx.x;
    const long base = row * DD + tid * 4;

    float4 r  = *(const float4*)&resid[base];
    float4 yv = *(const float4*)&y[base];
    float v0 = r.x + yv.x, v1 = r.y + yv.y, v2 = r.z + yv.z, v3 = r.w + yv.w;

    float s  = v0 + v1 + v2 + v3;
    float ss = v0*v0 + v1*v1 + v2*v2 + v3*v3;
    #pragma unroll
    for (int o = 16; o > 0; o >>= 1) {
        s  += __shfl_xor_sync(0xffffffffu, s, o);
        ss += __shfl_xor_sync(0xffffffffu, ss, o);
    }
    const int warp = tid >> 5;
    if ((tid & 31) == 0) {
        red[warp * 2]     = s;
        red[warp * 2 + 1] = ss;
    }
    __syncthreads();
    if (tid == 0) {
        float ts = 0.f, tss = 0.f;
        #pragma unroll
        for (int w = 0; w < 8; w++) { ts += red[w*2]; tss += red[w*2+1]; }
        float mean = ts * (1.0f / DD);
        float var  = tss * (1.0f / DD) - mean * mean;
        stats[0] = mean;
        stats[1] = rsqrtf(var + 1e-5f);
    }
    __syncthreads();
    const float mean = stats[0];
    const float istd = stats[1];

    float4 gv = *(const float4*)&g[tid * 4];
    float4 bv = *(const float4*)&beta[tid * 4];
    float4 o;
    o.x = (v0 - mean) * istd * gv.x + bv.x;
    o.y = (v1 - mean) * istd * gv.y + bv.y;
    o.z = (v2 - mean) * istd * gv.z + bv.z;
    o.w = (v3 - mean) * istd * gv.w + bv.w;
    *(float4*)&out[base] = o;
}

// ---------------------------------------------------------------------------
// Launcher
// ---------------------------------------------------------------------------
extern "C" void kernel_launch(void* const* d_in, const int* in_sizes, int n_in,
                              void* d_out, int out_size)
{
    const float* x      = (const float*)d_in[0];
    const float* imag   = (const float*)d_in[1];
    const float* w_qkv  = (const float*)d_in[2];
    const float* b_qkv  = (const float*)d_in[3];
    const float* w_o    = (const float*)d_in[4];
    const float* b_o    = (const float*)d_in[5];
    const float* ln1_g  = (const float*)d_in[6];
    const float* ln1_b  = (const float*)d_in[7];
    const float* w1     = (const float*)d_in[8];
    const float* b1     = (const float*)d_in[9];
    const float* w2     = (const float*)d_in[10];
    const float* b2     = (const float*)d_in[11];
    const float* ln2_g  = (const float*)d_in[12];
    const float* ln2_b  = (const float*)d_in[13];
    float* out = (float*)d_out;

    float *qkvp, *hopp, *attnp, *att2p, *x1p, *f1p, *f2p;
    cudaGetSymbolAddress((void**)&qkvp,  g_qkv);
    cudaGetSymbolAddress((void**)&hopp,  g_hop);
    cudaGetSymbolAddress((void**)&attnp, g_attn);
    cudaGetSymbolAddress((void**)&att2p, g_att2);
    cudaGetSymbolAddress((void**)&x1p,   g_x1);
    cudaGetSymbolAddress((void**)&f1p,   g_ff1);
    cudaGetSymbolAddress((void**)&f2p,   g_ff2);

    cudaFuncSetAttribute(sgemm_bt<false>,
                         cudaFuncAttributeMaxDynamicSharedMemorySize, GEMM_SMEM);
    cudaFuncSetAttribute(sgemm_bt<true>,
                         cudaFuncAttributeMaxDynamicSharedMemorySize, GEMM_SMEM);

    const int MR = BB * SS;  // 8192 rows

    // 1) hopping[b] = imag[b] @ imag[b]^T / sqrt(D)  (lower-triangular tiles)
    sgemm_bt<false><<<dim3(SS/128, SS/128, BB), 256, GEMM_SMEM>>>(
        imag, imag, nullptr, hopp, SS, SS, DD,
        (long)SS * DD, (long)SS * DD, (long)SS * SS, 0.03125f, 1);

    // 2) QKV projection
    sgemm_bt<false><<<dim3(3*DD/128, MR/128, 1), 256, GEMM_SMEM>>>(
        x, w_qkv, b_qkv, qkvp, MR, 3*DD, DD, 0, 0, 0, 1.0f, 0);

    // 3) Tensor-core causal attention with hopping bias
    attn_kernel<<<dim3(SS/64, HH, BB), 128>>>(qkvp, hopp, attnp);

    // 4) Output projection
    sgemm_bt<false><<<dim3(DD/128, MR/128, 1), 256, GEMM_SMEM>>>(
        attnp, w_o, b_o, att2p, MR, DD, DD, 0, 0, 0, 1.0f, 0);

    // 5) LN1(x + attn_out)
    ln_kernel<<<MR, 256>>>(x, att2p, ln1_g, ln1_b, x1p);

    // 6) FFN1 + exact GELU
    sgemm_bt<true><<<dim3(4*DD/128, MR/128, 1), 256, GEMM_SMEM>>>(
        x1p, w1, b1, f1p, MR, 4*DD, DD, 0, 0, 0, 1.0f, 0);

    // 7) FFN2
    sgemm_bt<false><<<dim3(DD/128, MR/128, 1), 256, GEMM_SMEM>>>(
        f1p, w2, b2, f2p, MR, DD, 4*DD, 0, 0, 0, 1.0f, 0);

    // 8) LN2(x1 + ffn_out) -> output
    ln_kernel<<<MR, 256>>>(x1p, f2p, ln2_g, ln2_b, out);
}